// round 6
// baseline (speedup 1.0000x reference)
#include <cuda_runtime.h>

// Problem constants
#define BB    16
#define TT    1000
#define FTOT  481
#define NF    96
#define NN    5          // FRAME_SIZE
#define NCOEF 30         // N*N + N
#define TF    (TT * NF)  // 96000

struct cplx { float re, im; };

__device__ __forceinline__ cplx cmul(cplx a, cplx b) {
    return { a.re * b.re - a.im * b.im, a.re * b.im + a.im * b.re };
}
__device__ __forceinline__ cplx csub(cplx a, cplx b) {
    return { a.re - b.re, a.im - b.im };
}
__device__ __forceinline__ cplx cdiv(cplx a, cplx b) {
    float inv = __frcp_rn(b.re * b.re + b.im * b.im);
    return { (a.re * b.re + a.im * b.im) * inv,
             (a.im * b.re - a.re * b.im) * inv };
}
__device__ __forceinline__ float cabs2(cplx a) { return a.re * a.re + a.im * a.im; }

// Rare fallback: full Gaussian elimination with partial pivoting.
// Reloads the system from coefs (L2-hot: same lines were just read).
// __noinline__ keeps the hot path's code and register footprint tight.
__device__ __noinline__ void solve_pivoted(const float2* __restrict__ coefs,
                                           int base, cplx w[NN]) {
    cplx A[NN][NN];
    cplx r[NN];
#pragma unroll
    for (int n = 0; n < NN; n++)
#pragma unroll
        for (int m = 0; m < NN; m++) {
            float2 v = coefs[base + (n * NN + m) * TF];
            A[n][m] = { v.x, v.y };
        }
#pragma unroll
    for (int n = 0; n < NN; n++) {
        float2 v = coefs[base + (NN * NN + n) * TF];
        r[n] = { v.x, v.y };
    }

#pragma unroll
    for (int k = 0; k < NN; k++) {
        // bubble max-magnitude pivot into row k (active columns only)
#pragma unroll
        for (int i = k + 1; i < NN; i++) {
            if (cabs2(A[i][k]) > cabs2(A[k][k])) {
#pragma unroll
                for (int j = k; j < NN; j++) {
                    cplx tmp = A[k][j]; A[k][j] = A[i][j]; A[i][j] = tmp;
                }
                cplx tmp = r[k]; r[k] = r[i]; r[i] = tmp;
            }
        }
        float pinv = __frcp_rn(cabs2(A[k][k]));
        cplx prec = { A[k][k].re * pinv, -A[k][k].im * pinv };
#pragma unroll
        for (int i = k + 1; i < NN; i++) {
            cplx fac = cmul(A[i][k], prec);
#pragma unroll
            for (int j = k + 1; j < NN; j++)
                A[i][j] = csub(A[i][j], cmul(fac, A[k][j]));
            r[i] = csub(r[i], cmul(fac, r[k]));
        }
    }
#pragma unroll
    for (int k = NN - 1; k >= 0; k--) {
        cplx s = r[k];
#pragma unroll
        for (int j = NN - 1; j > k; j--)
            s = csub(s, cmul(A[k][j], w[j]));
        w[k] = cdiv(s, A[k][k]);
    }
}

// Fused kernel: one thread per output float2 element (b, t, f), f in [0, 481).
//   f <  96 : solve 5x5 complex system from coefs, apply FIR over 5 time taps.
//   f >= 96 : pass-through copy of spec.
__global__ __launch_bounds__(128)
void mfwf_fused_kernel(const float2* __restrict__ spec,
                       const float2* __restrict__ coefs,
                       float2* __restrict__ out) {
    int g = blockIdx.x * blockDim.x + threadIdx.x;
    if (g >= BB * TT * FTOT) return;

    int bt = g / FTOT;          // b * TT + t
    int f  = g - bt * FTOT;

    if (f >= NF) {
        out[g] = spec[g];       // pass-through
        return;
    }

    int b = bt / TT;
    int t = bt - b * TT;
    int tf = t * NF + f;

    // ---- Load augmented system [A | r] (tf contiguous per (b,k) slab) ----
    cplx A[NN][NN];
    cplx r[NN];
    int base = b * NCOEF * TF + tf;
#pragma unroll
    for (int n = 0; n < NN; n++)
#pragma unroll
        for (int m = 0; m < NN; m++) {
            float2 v = coefs[base + (n * NN + m) * TF];
            A[n][m] = { v.x, v.y };
        }
#pragma unroll
    for (int n = 0; n < NN; n++) {
        float2 v = coefs[base + (NN * NN + n) * TF];
        r[n] = { v.x, v.y };
    }

    // ---- Fast path: GE without pivoting + stability flag ----
    bool bad = false;
#pragma unroll
    for (int k = 0; k < NN; k++) {
        float pa = cabs2(A[k][k]);
        float mx = pa;
#pragma unroll
        for (int i = k + 1; i < NN; i++) mx = fmaxf(mx, cabs2(A[i][k]));
        bad = bad || (pa * 1e6f < mx);     // pivot << column max => unstable

        float pinv = __frcp_rn(pa);
        cplx prec = { A[k][k].re * pinv, -A[k][k].im * pinv };
#pragma unroll
        for (int i = k + 1; i < NN; i++) {
            cplx fac = cmul(A[i][k], prec);
#pragma unroll
            for (int j = k + 1; j < NN; j++)
                A[i][j] = csub(A[i][j], cmul(fac, A[k][j]));
            r[i] = csub(r[i], cmul(fac, r[k]));
        }
    }

    cplx w[NN];
#pragma unroll
    for (int k = NN - 1; k >= 0; k--) {
        cplx s = r[k];
#pragma unroll
        for (int j = NN - 1; j > k; j--)
            s = csub(s, cmul(A[k][j], w[j]));
        w[k] = cdiv(s, A[k][k]);
    }

    // ---- Rare fallback: redo with partial pivoting ----
    if (bad) solve_pivoted(coefs, base, w);

    // ---- y = sum_n x[t - 4 + n, f] * w[n] ----
    cplx y = { 0.f, 0.f };
#pragma unroll
    for (int n = 0; n < NN; n++) {
        int tt = t - (NN - 1) + n;
        if (tt >= 0) {
            float2 v = spec[(b * TT + tt) * FTOT + f];
            cplx x = { v.x, v.y };
            y.re = fmaf(x.re, w[n].re, fmaf(-x.im, w[n].im, y.re));
            y.im = fmaf(x.re, w[n].im, fmaf( x.im, w[n].re, y.im));
        }
    }

    out[g] = make_float2(y.re, y.im);
}

extern "C" void kernel_launch(void* const* d_in, const int* in_sizes, int n_in,
                              void* d_out, int out_size) {
    const float2* spec  = (const float2*)d_in[0];
    const float2* coefs = (const float2*)d_in[1];
    float2* out = (float2*)d_out;

    int total = BB * TT * FTOT;   // 7,696,000 float2 outputs
    int threads = 128;
    int blocks = (total + threads - 1) / threads;
    mfwf_fused_kernel<<<blocks, threads>>>(spec, coefs, out);
}

// round 8
// speedup vs baseline: 1.0673x; 1.0673x over previous
#include <cuda_runtime.h>

// Problem constants
#define BB    16
#define TT    1000
#define FTOT  481
#define NF    96
#define NN    5          // FRAME_SIZE
#define NCOEF 30         // N*N + N
#define TF    (TT * NF)  // 96000

struct cplx { float re, im; };

__device__ __forceinline__ cplx cmul(cplx a, cplx b) {
    return { a.re * b.re - a.im * b.im, a.re * b.im + a.im * b.re };
}
__device__ __forceinline__ cplx csub(cplx a, cplx b) {
    return { a.re - b.re, a.im - b.im };
}
__device__ __forceinline__ cplx cdiv(cplx a, cplx b) {
    float inv = __frcp_rn(b.re * b.re + b.im * b.im);
    return { (a.re * b.re + a.im * b.im) * inv,
             (a.im * b.re - a.re * b.im) * inv };
}
__device__ __forceinline__ float cabs2(cplx a) { return a.re * a.re + a.im * a.im; }

// Rare fallback: full Gaussian elimination with partial pivoting.
// Reloads the system from coefs (L2-hot: same lines were just read).
// __noinline__ keeps the hot path's code and register footprint tight.
__device__ __noinline__ void solve_pivoted(const float2* __restrict__ coefs,
                                           int base, cplx w[NN]) {
    cplx A[NN][NN];
    cplx r[NN];
#pragma unroll
    for (int n = 0; n < NN; n++)
#pragma unroll
        for (int m = 0; m < NN; m++) {
            float2 v = coefs[base + (n * NN + m) * TF];
            A[n][m] = { v.x, v.y };
        }
#pragma unroll
    for (int n = 0; n < NN; n++) {
        float2 v = coefs[base + (NN * NN + n) * TF];
        r[n] = { v.x, v.y };
    }

#pragma unroll
    for (int k = 0; k < NN; k++) {
        // bubble max-magnitude pivot into row k (active columns only)
#pragma unroll
        for (int i = k + 1; i < NN; i++) {
            if (cabs2(A[i][k]) > cabs2(A[k][k])) {
#pragma unroll
                for (int j = k; j < NN; j++) {
                    cplx tmp = A[k][j]; A[k][j] = A[i][j]; A[i][j] = tmp;
                }
                cplx tmp = r[k]; r[k] = r[i]; r[i] = tmp;
            }
        }
        float pinv = __frcp_rn(cabs2(A[k][k]));
        cplx prec = { A[k][k].re * pinv, -A[k][k].im * pinv };
#pragma unroll
        for (int i = k + 1; i < NN; i++) {
            cplx fac = cmul(A[i][k], prec);
#pragma unroll
            for (int j = k + 1; j < NN; j++)
                A[i][j] = csub(A[i][j], cmul(fac, A[k][j]));
            r[i] = csub(r[i], cmul(fac, r[k]));
        }
    }
#pragma unroll
    for (int k = NN - 1; k >= 0; k--) {
        cplx s = r[k];
#pragma unroll
        for (int j = NN - 1; j > k; j--)
            s = csub(s, cmul(A[k][j], w[j]));
        w[k] = cdiv(s, A[k][k]);
    }
}

// Fused kernel: one thread per output float2 element (b, t, f), f in [0, 481).
//   f <  96 : solve 5x5 complex system from coefs, apply FIR over 5 time taps.
//   f >= 96 : pass-through copy of spec.
__global__ __launch_bounds__(128)
void mfwf_fused_kernel(const float2* __restrict__ spec,
                       const float2* __restrict__ coefs,
                       float2* __restrict__ out) {
    int g = blockIdx.x * blockDim.x + threadIdx.x;
    if (g >= BB * TT * FTOT) return;

    int bt = g / FTOT;          // b * TT + t
    int f  = g - bt * FTOT;

    if (f >= NF) {
        out[g] = spec[g];       // pass-through
        return;
    }

    int b = bt / TT;
    int t = bt - b * TT;
    int tf = t * NF + f;

    // ---- Hoist the 5 spec FIR taps to the front: these loads overlap the
    //      entire solve phase instead of serializing after it. ----
    cplx xtap[NN];
#pragma unroll
    for (int n = 0; n < NN; n++) {
        int tt = t - (NN - 1) + n;
        if (tt >= 0) {
            float2 v = spec[(b * TT + tt) * FTOT + f];
            xtap[n] = { v.x, v.y };
        } else {
            xtap[n] = { 0.f, 0.f };
        }
    }

    // ---- Load augmented system [A | r] (tf contiguous per (b,k) slab) ----
    cplx A[NN][NN];
    cplx r[NN];
    int base = b * NCOEF * TF + tf;
#pragma unroll
    for (int n = 0; n < NN; n++)
#pragma unroll
        for (int m = 0; m < NN; m++) {
            float2 v = coefs[base + (n * NN + m) * TF];
            A[n][m] = { v.x, v.y };
        }
#pragma unroll
    for (int n = 0; n < NN; n++) {
        float2 v = coefs[base + (NN * NN + n) * TF];
        r[n] = { v.x, v.y };
    }

    // ---- Fast path: GE without pivoting + stability flag ----
    bool bad = false;
#pragma unroll
    for (int k = 0; k < NN; k++) {
        float pa = cabs2(A[k][k]);
        float mx = pa;
#pragma unroll
        for (int i = k + 1; i < NN; i++) mx = fmaxf(mx, cabs2(A[i][k]));
        bad = bad || (pa * 1e6f < mx);     // pivot << column max => unstable

        float pinv = __frcp_rn(pa);
        cplx prec = { A[k][k].re * pinv, -A[k][k].im * pinv };
#pragma unroll
        for (int i = k + 1; i < NN; i++) {
            cplx fac = cmul(A[i][k], prec);
#pragma unroll
            for (int j = k + 1; j < NN; j++)
                A[i][j] = csub(A[i][j], cmul(fac, A[k][j]));
            r[i] = csub(r[i], cmul(fac, r[k]));
        }
    }

    cplx w[NN];
#pragma unroll
    for (int k = NN - 1; k >= 0; k--) {
        cplx s = r[k];
#pragma unroll
        for (int j = NN - 1; j > k; j--)
            s = csub(s, cmul(A[k][j], w[j]));
        w[k] = cdiv(s, A[k][k]);
    }

    // ---- Rare fallback: redo with partial pivoting ----
    if (bad) solve_pivoted(coefs, base, w);

    // ---- y = sum_n xtap[n] * w[n] ----
    cplx y = { 0.f, 0.f };
#pragma unroll
    for (int n = 0; n < NN; n++) {
        y.re = fmaf(xtap[n].re, w[n].re, fmaf(-xtap[n].im, w[n].im, y.re));
        y.im = fmaf(xtap[n].re, w[n].im, fmaf( xtap[n].im, w[n].re, y.im));
    }

    out[g] = make_float2(y.re, y.im);
}

extern "C" void kernel_launch(void* const* d_in, const int* in_sizes, int n_in,
                              void* d_out, int out_size) {
    const float2* spec  = (const float2*)d_in[0];
    const float2* coefs = (const float2*)d_in[1];
    float2* out = (float2*)d_out;

    int total = BB * TT * FTOT;   // 7,696,000 float2 outputs
    int threads = 128;
    int blocks = (total + threads - 1) / threads;
    mfwf_fused_kernel<<<blocks, threads>>>(spec, coefs, out);
}

// round 9
// speedup vs baseline: 1.1881x; 1.1131x over previous
#include <cuda_runtime.h>
#include <cstdint>

// Problem constants
#define BB    16
#define TT    1000
#define FTOT  481
#define NF    96
#define NN    5          // FRAME_SIZE
#define NCOEF 30         // N*N + N
#define TF    (TT * NF)  // 96000

struct cplx { float re, im; };

__device__ __forceinline__ cplx cmul(cplx a, cplx b) {
    return { a.re * b.re - a.im * b.im, a.re * b.im + a.im * b.re };
}
__device__ __forceinline__ cplx csub(cplx a, cplx b) {
    return { a.re - b.re, a.im - b.im };
}
__device__ __forceinline__ cplx cdiv(cplx a, cplx b) {
    float inv = __frcp_rn(b.re * b.re + b.im * b.im);
    return { (a.re * b.re + a.im * b.im) * inv,
             (a.im * b.re - a.re * b.im) * inv };
}
__device__ __forceinline__ float cabs2(cplx a) { return a.re * a.re + a.im * a.im; }

__device__ __forceinline__ uint32_t smem_u32(const void* p) {
    uint32_t a;
    asm("{ .reg .u64 t; cvta.to.shared.u64 t, %1; cvt.u32.u64 %0, t; }"
        : "=r"(a) : "l"(p));
    return a;
}

// Rare fallback: full Gaussian elimination with partial pivoting.
// Reloads the system from coefs (L2-hot: same lines were just read).
__device__ __noinline__ void solve_pivoted(const float2* __restrict__ coefs,
                                           int base, cplx w[NN]) {
    cplx A[NN][NN];
    cplx r[NN];
#pragma unroll
    for (int n = 0; n < NN; n++)
#pragma unroll
        for (int m = 0; m < NN; m++) {
            float2 v = coefs[base + (n * NN + m) * TF];
            A[n][m] = { v.x, v.y };
        }
#pragma unroll
    for (int n = 0; n < NN; n++) {
        float2 v = coefs[base + (NN * NN + n) * TF];
        r[n] = { v.x, v.y };
    }

#pragma unroll
    for (int k = 0; k < NN; k++) {
#pragma unroll
        for (int i = k + 1; i < NN; i++) {
            if (cabs2(A[i][k]) > cabs2(A[k][k])) {
#pragma unroll
                for (int j = k; j < NN; j++) {
                    cplx tmp = A[k][j]; A[k][j] = A[i][j]; A[i][j] = tmp;
                }
                cplx tmp = r[k]; r[k] = r[i]; r[i] = tmp;
            }
        }
        float pinv = __frcp_rn(cabs2(A[k][k]));
        cplx prec = { A[k][k].re * pinv, -A[k][k].im * pinv };
#pragma unroll
        for (int i = k + 1; i < NN; i++) {
            cplx fac = cmul(A[i][k], prec);
#pragma unroll
            for (int j = k + 1; j < NN; j++)
                A[i][j] = csub(A[i][j], cmul(fac, A[k][j]));
            r[i] = csub(r[i], cmul(fac, r[k]));
        }
    }
#pragma unroll
    for (int k = NN - 1; k >= 0; k--) {
        cplx s = r[k];
#pragma unroll
        for (int j = NN - 1; j > k; j--)
            s = csub(s, cmul(A[k][j], w[j]));
        w[k] = cdiv(s, A[k][k]);
    }
}

// Fused kernel: one thread per output float2 element (b, t, f), f in [0, 481).
//   f <  96 : solve 5x5 complex system from coefs, apply FIR over 5 time taps.
//   f >= 96 : pass-through copy of spec.
// Spec FIR taps are staged in shared memory via cp.async: issued up front so
// they overlap the solve, but consume no data registers during it.
__global__ __launch_bounds__(128, 6)
void mfwf_fused_kernel(const float2* __restrict__ spec,
                       const float2* __restrict__ coefs,
                       float2* __restrict__ out) {
    __shared__ float2 taps[NN][128];   // SoA: conflict-free 64-bit LDS

    int g = blockIdx.x * blockDim.x + threadIdx.x;
    if (g >= BB * TT * FTOT) return;

    int bt = g / FTOT;          // b * TT + t
    int f  = g - bt * FTOT;

    if (f >= NF) {
        out[g] = spec[g];       // pass-through
        return;
    }

    int b = bt / TT;
    int t = bt - b * TT;
    int tf = t * NF + f;
    int tid = threadIdx.x;

    // ---- Stage the 5 spec FIR taps into smem via cp.async (no data regs) ----
#pragma unroll
    for (int n = 0; n < NN; n++) {
        uint32_t saddr = smem_u32(&taps[n][tid]);
        int tt = t - (NN - 1) + n;
        if (tt >= 0) {
            const float2* gptr = &spec[(b * TT + tt) * FTOT + f];
            asm volatile("cp.async.ca.shared.global [%0], [%1], 8;\n"
                         :: "r"(saddr), "l"(gptr) : "memory");
        } else {
            asm volatile("st.shared.v2.f32 [%0], {%1, %2};\n"
                         :: "r"(saddr), "f"(0.f), "f"(0.f) : "memory");
        }
    }
    asm volatile("cp.async.commit_group;\n" ::: "memory");

    // ---- Load augmented system [A | r] (tf contiguous per (b,k) slab) ----
    cplx A[NN][NN];
    cplx r[NN];
    int base = b * NCOEF * TF + tf;
#pragma unroll
    for (int n = 0; n < NN; n++)
#pragma unroll
        for (int m = 0; m < NN; m++) {
            float2 v = coefs[base + (n * NN + m) * TF];
            A[n][m] = { v.x, v.y };
        }
#pragma unroll
    for (int n = 0; n < NN; n++) {
        float2 v = coefs[base + (NN * NN + n) * TF];
        r[n] = { v.x, v.y };
    }

    // ---- Fast path: GE without pivoting + stability flag ----
    bool bad = false;
#pragma unroll
    for (int k = 0; k < NN; k++) {
        float pa = cabs2(A[k][k]);
        float mx = pa;
#pragma unroll
        for (int i = k + 1; i < NN; i++) mx = fmaxf(mx, cabs2(A[i][k]));
        bad = bad || (pa * 1e6f < mx);     // pivot << column max => unstable

        float pinv = __frcp_rn(pa);
        cplx prec = { A[k][k].re * pinv, -A[k][k].im * pinv };
#pragma unroll
        for (int i = k + 1; i < NN; i++) {
            cplx fac = cmul(A[i][k], prec);
#pragma unroll
            for (int j = k + 1; j < NN; j++)
                A[i][j] = csub(A[i][j], cmul(fac, A[k][j]));
            r[i] = csub(r[i], cmul(fac, r[k]));
        }
    }

    cplx w[NN];
#pragma unroll
    for (int k = NN - 1; k >= 0; k--) {
        cplx s = r[k];
#pragma unroll
        for (int j = NN - 1; j > k; j--)
            s = csub(s, cmul(A[k][j], w[j]));
        w[k] = cdiv(s, A[k][k]);
    }

    // ---- Rare fallback: redo with partial pivoting ----
    if (bad) solve_pivoted(coefs, base, w);

    // ---- Wait for staged taps (thread-local visibility, no barrier needed) ----
    asm volatile("cp.async.wait_group 0;\n" ::: "memory");

    // ---- y = sum_n taps[n] * w[n] ----
    cplx y = { 0.f, 0.f };
#pragma unroll
    for (int n = 0; n < NN; n++) {
        float2 v = taps[n][tid];
        y.re = fmaf(v.x, w[n].re, fmaf(-v.y, w[n].im, y.re));
        y.im = fmaf(v.x, w[n].im, fmaf( v.y, w[n].re, y.im));
    }

    out[g] = make_float2(y.re, y.im);
}

extern "C" void kernel_launch(void* const* d_in, const int* in_sizes, int n_in,
                              void* d_out, int out_size) {
    const float2* spec  = (const float2*)d_in[0];
    const float2* coefs = (const float2*)d_in[1];
    float2* out = (float2*)d_out;

    int total = BB * TT * FTOT;   // 7,696,000 float2 outputs
    int threads = 128;
    int blocks = (total + threads - 1) / threads;
    mfwf_fused_kernel<<<blocks, threads>>>(spec, coefs, out);
}

// round 10
// speedup vs baseline: 1.3733x; 1.1559x over previous
#include <cuda_runtime.h>
#include <cstdint>

// Problem constants
#define BB    16
#define TT    1000
#define FTOT  481
#define NF    96
#define NN    5          // FRAME_SIZE
#define NCOEF 30         // N*N + N
#define TF    (TT * NF)  // 96000

struct cplx { float re, im; };

__device__ __forceinline__ cplx cmul(cplx a, cplx b) {
    return { a.re * b.re - a.im * b.im, a.re * b.im + a.im * b.re };
}
__device__ __forceinline__ cplx csub(cplx a, cplx b) {
    return { a.re - b.re, a.im - b.im };
}
__device__ __forceinline__ cplx cdiv(cplx a, cplx b) {
    float inv = __frcp_rn(b.re * b.re + b.im * b.im);
    return { (a.re * b.re + a.im * b.im) * inv,
             (a.im * b.re - a.re * b.im) * inv };
}
__device__ __forceinline__ float cabs2(cplx a) { return a.re * a.re + a.im * a.im; }

__device__ __forceinline__ uint32_t smem_u32(const void* p) {
    uint32_t a;
    asm("{ .reg .u64 t; cvta.to.shared.u64 t, %1; cvt.u32.u64 %0, t; }"
        : "=r"(a) : "l"(p));
    return a;
}

// Rare fallback: full Gaussian elimination with partial pivoting.
// Reloads the system from coefs (L2-hot: same lines were just read).
__device__ __noinline__ void solve_pivoted(const float2* __restrict__ coefs,
                                           int base, cplx w[NN]) {
    cplx A[NN][NN];
    cplx r[NN];
#pragma unroll
    for (int n = 0; n < NN; n++)
#pragma unroll
        for (int m = 0; m < NN; m++) {
            float2 v = coefs[base + (n * NN + m) * TF];
            A[n][m] = { v.x, v.y };
        }
#pragma unroll
    for (int n = 0; n < NN; n++) {
        float2 v = coefs[base + (NN * NN + n) * TF];
        r[n] = { v.x, v.y };
    }

#pragma unroll
    for (int k = 0; k < NN; k++) {
#pragma unroll
        for (int i = k + 1; i < NN; i++) {
            if (cabs2(A[i][k]) > cabs2(A[k][k])) {
#pragma unroll
                for (int j = k; j < NN; j++) {
                    cplx tmp = A[k][j]; A[k][j] = A[i][j]; A[i][j] = tmp;
                }
                cplx tmp = r[k]; r[k] = r[i]; r[i] = tmp;
            }
        }
        float pinv = __frcp_rn(cabs2(A[k][k]));
        cplx prec = { A[k][k].re * pinv, -A[k][k].im * pinv };
#pragma unroll
        for (int i = k + 1; i < NN; i++) {
            cplx fac = cmul(A[i][k], prec);
#pragma unroll
            for (int j = k + 1; j < NN; j++)
                A[i][j] = csub(A[i][j], cmul(fac, A[k][j]));
            r[i] = csub(r[i], cmul(fac, r[k]));
        }
    }
#pragma unroll
    for (int k = NN - 1; k >= 0; k--) {
        cplx s = r[k];
#pragma unroll
        for (int j = NN - 1; j > k; j--)
            s = csub(s, cmul(A[k][j], w[j]));
        w[k] = cdiv(s, A[k][k]);
    }
}

// Fused kernel: one thread per output float2 element (b, t, f), f in [0, 481).
//   f <  96 : LU-solve 5x5 complex system from coefs, FIR over 5 time taps.
//   f >= 96 : pass-through copy of spec.
// rss (r) and spec taps staged in smem via cp.async so that (a) their loads
// overlap the LU, and (b) only A's 50 floats are register-live during it.
__global__ __launch_bounds__(128, 8)
void mfwf_fused_kernel(const float2* __restrict__ spec,
                       const float2* __restrict__ coefs,
                       float2* __restrict__ out) {
    __shared__ float2 s_r[NN][128];     // rss
    __shared__ float2 s_tap[NN][128];   // spec FIR taps

    int g = blockIdx.x * blockDim.x + threadIdx.x;
    if (g >= BB * TT * FTOT) return;

    int bt = g / FTOT;          // b * TT + t
    int f  = g - bt * FTOT;

    if (f >= NF) {
        out[g] = spec[g];       // pass-through
        return;
    }

    int b = bt / TT;
    int t = bt - b * TT;
    int tf = t * NF + f;
    int tid = threadIdx.x;
    int base = b * NCOEF * TF + tf;

    // ---- Group 0: stage rss into smem ----
#pragma unroll
    for (int n = 0; n < NN; n++) {
        uint32_t saddr = smem_u32(&s_r[n][tid]);
        const float2* gptr = &coefs[base + (NN * NN + n) * TF];
        asm volatile("cp.async.ca.shared.global [%0], [%1], 8;\n"
                     :: "r"(saddr), "l"(gptr) : "memory");
    }
    asm volatile("cp.async.commit_group;\n" ::: "memory");

    // ---- Group 1: stage spec FIR taps into smem ----
#pragma unroll
    for (int n = 0; n < NN; n++) {
        uint32_t saddr = smem_u32(&s_tap[n][tid]);
        int tt = t - (NN - 1) + n;
        if (tt >= 0) {
            const float2* gptr = &spec[(b * TT + tt) * FTOT + f];
            asm volatile("cp.async.ca.shared.global [%0], [%1], 8;\n"
                         :: "r"(saddr), "l"(gptr) : "memory");
        } else {
            asm volatile("st.shared.v2.f32 [%0], {%1, %2};\n"
                         :: "r"(saddr), "f"(0.f), "f"(0.f) : "memory");
        }
    }
    asm volatile("cp.async.commit_group;\n" ::: "memory");

    // ---- Load Rxx (25 complexes; only these are register-live in the LU) ----
    cplx A[NN][NN];
#pragma unroll
    for (int n = 0; n < NN; n++)
#pragma unroll
        for (int m = 0; m < NN; m++) {
            float2 v = coefs[base + (n * NN + m) * TF];
            A[n][m] = { v.x, v.y };
        }

    // ---- In-place LU (no pivoting) + stability flag; multipliers in lower tri ----
    bool bad = false;
#pragma unroll
    for (int k = 0; k < NN; k++) {
        float pa = cabs2(A[k][k]);
        float mx = pa;
#pragma unroll
        for (int i = k + 1; i < NN; i++) mx = fmaxf(mx, cabs2(A[i][k]));
        bad = bad || (pa * 1e6f < mx);     // pivot << column max => unstable

        float pinv = __frcp_rn(pa);
        cplx prec = { A[k][k].re * pinv, -A[k][k].im * pinv };
#pragma unroll
        for (int i = k + 1; i < NN; i++) {
            cplx fac = cmul(A[i][k], prec);
            A[i][k] = fac;                 // store multiplier in dead slot
#pragma unroll
            for (int j = k + 1; j < NN; j++)
                A[i][j] = csub(A[i][j], cmul(fac, A[k][j]));
        }
    }

    // ---- Wait for r (group 0 done; taps group may still be in flight) ----
    asm volatile("cp.async.wait_group 1;\n" ::: "memory");

    // ---- Forward substitution: y[i] = r[i] - sum_{k<i} L[i][k] * y[k] ----
    cplx y5[NN];
#pragma unroll
    for (int i = 0; i < NN; i++) {
        float2 v = s_r[i][tid];
        cplx s = { v.x, v.y };
#pragma unroll
        for (int k = 0; k < NN; k++)
            if (k < i) s = csub(s, cmul(A[i][k], y5[k]));
        y5[i] = s;
    }

    // ---- Back substitution: w[k] = (y[k] - sum_{j>k} U[k][j] w[j]) / U[k][k] ----
    cplx w[NN];
#pragma unroll
    for (int k = NN - 1; k >= 0; k--) {
        cplx s = y5[k];
#pragma unroll
        for (int j = NN - 1; j > k; j--)
            s = csub(s, cmul(A[k][j], w[j]));
        w[k] = cdiv(s, A[k][k]);
    }

    // ---- Rare fallback: redo with partial pivoting ----
    if (bad) solve_pivoted(coefs, base, w);

    // ---- Wait for taps, then y = sum_n tap[n] * w[n] ----
    asm volatile("cp.async.wait_group 0;\n" ::: "memory");

    cplx acc = { 0.f, 0.f };
#pragma unroll
    for (int n = 0; n < NN; n++) {
        float2 v = s_tap[n][tid];
        acc.re = fmaf(v.x, w[n].re, fmaf(-v.y, w[n].im, acc.re));
        acc.im = fmaf(v.x, w[n].im, fmaf( v.y, w[n].re, acc.im));
    }

    out[g] = make_float2(acc.re, acc.im);
}

extern "C" void kernel_launch(void* const* d_in, const int* in_sizes, int n_in,
                              void* d_out, int out_size) {
    const float2* spec  = (const float2*)d_in[0];
    const float2* coefs = (const float2*)d_in[1];
    float2* out = (float2*)d_out;

    int total = BB * TT * FTOT;   // 7,696,000 float2 outputs
    int threads = 128;
    int blocks = (total + threads - 1) / threads;
    mfwf_fused_kernel<<<blocks, threads>>>(spec, coefs, out);
}